// round 3
// baseline (speedup 1.0000x reference)
#include <cuda_runtime.h>

#define NODES 64
#define KNB   32
#define FEAT  1024
#define C1    4
#define F1    16
#define O1    64        // C1*F1
#define C2    32
#define NCLS  10
#define JDIM  33        // self + 32 neighbors
#define ATILE 128
#define ATILES 8        // FEAT / ATILE
#define BTILE 256
#define BN_EPS 1e-5f

// -------- scratch (no allocations allowed) --------
__device__ float g_S[NODES * FEAT];                       // 256 KB
__device__ float g_Pp[NODES * ATILES * O1 * JDIM];        // 4.3 MB partial W1@R
__device__ float g_P[NODES * O1 * JDIM];                  // 540 KB
__device__ float g_alpha[C1];
__device__ float g_beta[C1];
__device__ float g_x2p[NODES * C2];

// adj = s/(|s|+1e-7), s = sign(t)*sqrt(max(|t|,1e-8))
// => |adj| = 1/(1 + 1e-7 * rsqrt(max(|t|,1e-8)))
__device__ __forceinline__ float adjf(float t) {
    float m  = fmaxf(fabsf(t), 1e-8f);
    float rs = rsqrtf(m);
    float v  = __fdividef(1.0f, fmaf(1e-7f, rs, 1.0f));
    return (t > 0.0f) ? v : ((t < 0.0f) ? -v : 0.0f);
}

// K0: S[n,b] = sum_k nb[n,k,b]
__global__ void k0_sum_nb(const float* __restrict__ nb) {
    int n = blockIdx.x;
    for (int b = threadIdx.x; b < FEAT; b += 256) {
        float s = 0.0f;
        #pragma unroll 8
        for (int k = 0; k < KNB; k++) s += nb[(n * KNB + k) * FEAT + b];
        g_S[n * FEAT + b] = s;
    }
}

// K1: per (node, a-tile): R[a][j] = sum_b adj(a,b) * Y[j][b],  Y = [x ; nb_0..31]
// epilogue: partial P[o][j] = sum_{a in tile} W1[o][a] * R[a][j]
__global__ __launch_bounds__(128) void k1_main(
        const float* __restrict__ x,
        const float* __restrict__ nb,
        const float* __restrict__ W1) {
    __shared__ __align__(16) float smem[8704];   // 34.8 KB
    float* Ys = smem;                 // [33][256] phase A
    float* Ss = smem + JDIM * BTILE;  // [256]

    const int n   = blockIdx.y;
    const int at  = blockIdx.x;
    const int a0  = at * ATILE;
    const int tid = threadIdx.x;     // 128, one adjacency row each

    const float xa = x[n * FEAT + a0 + tid];
    const float Sa = g_S[n * FEAT + a0 + tid];

    float acc[JDIM];
    #pragma unroll
    for (int j = 0; j < JDIM; j++) acc[j] = 0.0f;

    const float* xrow   = x + n * FEAT;
    const float* nbbase = nb + n * KNB * FEAT;

    for (int bt = 0; bt < FEAT; bt += BTILE) {
        __syncthreads();
        // stage Y tile: 33 rows x 64 float4
        for (int idx = tid; idx < JDIM * (BTILE / 4); idx += 128) {
            int j = idx >> 6, q = idx & 63;
            const float* src = (j == 0 ? xrow : nbbase + (j - 1) * FEAT) + bt + q * 4;
            ((float4*)Ys)[idx] = *(const float4*)src;
        }
        for (int idx = tid; idx < BTILE / 4; idx += 128)
            ((float4*)Ss)[idx] = *(const float4*)(g_S + n * FEAT + bt + idx * 4);
        __syncthreads();

        #pragma unroll 1
        for (int q = 0; q < BTILE / 4; q++) {
            float4 xb = ((float4*)Ys)[q];   // row j=0 is x
            float4 Sb = ((float4*)Ss)[q];
            float a0v = adjf(fmaf(xa, Sb.x, xb.x * Sa));
            float a1v = adjf(fmaf(xa, Sb.y, xb.y * Sa));
            float a2v = adjf(fmaf(xa, Sb.z, xb.z * Sa));
            float a3v = adjf(fmaf(xa, Sb.w, xb.w * Sa));
            #pragma unroll
            for (int j = 0; j < JDIM; j++) {
                float4 y = ((float4*)Ys)[j * 64 + q];   // broadcast
                float t = acc[j];
                t = fmaf(a0v, y.x, t);
                t = fmaf(a1v, y.y, t);
                t = fmaf(a2v, y.z, t);
                t = fmaf(a3v, y.w, t);
                acc[j] = t;
            }
        }
    }

    // ---- epilogue: fold W1 over this a-tile ----
    __syncthreads();
    float* Rs = smem;                // [128][34]
    float* Wt = smem + ATILE * 34;   // [32][129]
    #pragma unroll
    for (int j = 0; j < JDIM; j++) Rs[tid * 34 + j] = acc[j];
    __syncthreads();

    for (int ot = 0; ot < O1; ot += 32) {
        for (int idx = tid; idx < 32 * ATILE; idx += 128) {
            int oo = idx >> 7, i = idx & 127;
            Wt[oo * 129 + i] = W1[(ot + oo) * FEAT + a0 + i];
        }
        __syncthreads();
        for (int out = tid; out < 32 * JDIM; out += 128) {
            int oo = out / JDIM, j = out - oo * JDIM;
            float s0 = 0.0f, s1 = 0.0f;
            #pragma unroll 4
            for (int i = 0; i < ATILE; i += 2) {
                s0 = fmaf(Wt[oo * 129 + i],     Rs[i * 34 + j],       s0);
                s1 = fmaf(Wt[oo * 129 + i + 1], Rs[(i + 1) * 34 + j], s1);
            }
            g_Pp[((n * ATILES + at) * O1 + (ot + oo)) * JDIM + j] = s0 + s1;
        }
        __syncthreads();
    }
}

// K2r: P[n] = sum over 8 a-tile partials
__global__ void k2_reduce() {
    int n = blockIdx.x;
    for (int oj = threadIdx.x; oj < O1 * JDIM; oj += 256) {
        float s = 0.0f;
        #pragma unroll
        for (int sl = 0; sl < ATILES; sl++)
            s += g_Pp[(n * ATILES + sl) * O1 * JDIM + oj];
        g_P[n * O1 * JDIM + oj] = s;
    }
}

// K3a: BN1 stats for x-path (per channel over all nodes & features)
__global__ void k3a_bn1x(const float* __restrict__ bn1w, const float* __restrict__ bn1b) {
    __shared__ float rs[8], rq[8];
    int tid = threadIdx.x;           // 256
    int c = tid >> 6, r = tid & 63;  // node r, channel c
    float s = 0.0f, q = 0.0f;
    #pragma unroll
    for (int f = 0; f < F1; f++) {
        float v = g_P[r * O1 * JDIM + (c * F1 + f) * JDIM];  // j=0
        s += v; q += v * v;
    }
    for (int off = 16; off; off >>= 1) {
        s += __shfl_down_sync(0xffffffffu, s, off);
        q += __shfl_down_sync(0xffffffffu, q, off);
    }
    if ((tid & 31) == 0) { rs[tid >> 5] = s; rq[tid >> 5] = q; }
    __syncthreads();
    if (tid < C1) {
        float S = rs[2 * tid] + rs[2 * tid + 1];
        float Q = rq[2 * tid] + rq[2 * tid + 1];
        float m = S * (1.0f / 1024.0f);
        float v = Q * (1.0f / 1024.0f) - m * m;
        float al = bn1w[tid] * rsqrtf(v + BN_EPS);
        g_alpha[tid] = al;
        g_beta[tid]  = bn1b[tid] - m * al;
    }
}

// K3b: per node — nb BN (per-node stats) + full layer 2 up to pre-BN2 x2
__global__ __launch_bounds__(128) void k3b_layer2(
        const float* __restrict__ W2,
        const float* __restrict__ bn1w, const float* __restrict__ bn1b) {
    int n = blockIdx.x, tid = threadIdx.x;
    __shared__ float Ps[O1 * JDIM];
    __shared__ float x1s[O1];
    __shared__ float nb1s[KNB * O1];
    __shared__ float S2s[O1];
    __shared__ float xa2s[O1];

    for (int i = tid; i < O1 * JDIM; i += 128) Ps[i] = g_P[n * O1 * JDIM + i];
    __syncthreads();

    if (tid < O1) {
        int c = tid >> 4;
        float y = fmaf(g_alpha[c], Ps[tid * JDIM], g_beta[c]);
        x1s[tid] = __fdividef(y, 1.0f + fabsf(y));
    }
    // neighbor BN: one warp per channel, lane = k
    {
        int c = tid >> 5, k = tid & 31;
        float s = 0.0f, q = 0.0f;
        #pragma unroll
        for (int f = 0; f < F1; f++) {
            float v = Ps[(c * F1 + f) * JDIM + 1 + k];
            s += v; q += v * v;
        }
        for (int off = 16; off; off >>= 1) {
            s += __shfl_down_sync(0xffffffffu, s, off);
            q += __shfl_down_sync(0xffffffffu, q, off);
        }
        float al = 0.0f, be = 0.0f;
        if (k == 0) {
            float m = s * (1.0f / 512.0f);
            float v = q * (1.0f / 512.0f) - m * m;
            al = bn1w[c] * rsqrtf(v + BN_EPS);
            be = bn1b[c] - m * al;
        }
        al = __shfl_sync(0xffffffffu, al, 0);
        be = __shfl_sync(0xffffffffu, be, 0);
        #pragma unroll
        for (int f = 0; f < F1; f++) {
            float y = fmaf(al, Ps[(c * F1 + f) * JDIM + 1 + k], be);
            nb1s[k * O1 + c * F1 + f] = __fdividef(y, 1.0f + fabsf(y));
        }
    }
    __syncthreads();
    if (tid < O1) {
        float s = 0.0f;
        #pragma unroll 8
        for (int k = 0; k < KNB; k++) s += nb1s[k * O1 + tid];
        S2s[tid] = s;
    }
    __syncthreads();
    // adj2 (denominator couples the 4 channels) fused into xa2
    if (tid < O1) {
        int c = tid >> 4, a = tid & 15;
        float acc = 0.0f;
        for (int b = 0; b < F1; b++) {
            float denom = 1e-7f, sc = 0.0f;
            #pragma unroll
            for (int c2 = 0; c2 < C1; c2++) {
                float t = x1s[c2 * F1 + a] * S2s[c2 * F1 + b]
                        + x1s[c2 * F1 + b] * S2s[c2 * F1 + a];
                float m = fmaxf(fabsf(t), 1e-8f);
                float r = m * rsqrtf(m);                 // sqrt(m)
                float sv = (t > 0.0f) ? r : ((t < 0.0f) ? -r : 0.0f);
                if (c2 == c) sc = sv;
                denom += fabsf(sv);
            }
            acc += __fdividef(sc, denom) * x1s[c * F1 + b];
        }
        xa2s[tid] = acc;
    }
    __syncthreads();
    if (tid < C2) {
        float s = 0.0f;
        #pragma unroll 8
        for (int i = 0; i < O1; i++) s = fmaf(W2[tid * O1 + i], xa2s[i], s);
        g_x2p[n * C2 + tid] = s;
    }
}

// K3c: BN2 (per channel over nodes) + softsign + final linear
__global__ void k3c_final(const float* __restrict__ bn2w, const float* __restrict__ bn2b,
                          const float* __restrict__ linw, const float* __restrict__ linb,
                          float* __restrict__ out) {
    __shared__ float Ysm[NODES * C2];
    __shared__ float als[C2], bes[C2];
    int tid = threadIdx.x;  // 256
    if (tid < C2) {
        float s = 0.0f, q = 0.0f;
        for (int nn = 0; nn < NODES; nn++) {
            float v = g_x2p[nn * C2 + tid];
            s += v; q += v * v;
        }
        float m = s * (1.0f / 64.0f);
        float v = q * (1.0f / 64.0f) - m * m;
        float al = bn2w[tid] * rsqrtf(v + BN_EPS);
        als[tid] = al;
        bes[tid] = bn2b[tid] - m * al;
    }
    __syncthreads();
    for (int i = tid; i < NODES * C2; i += 256) {
        int o = i & (C2 - 1);
        float y = fmaf(als[o], g_x2p[i], bes[o]);
        Ysm[i] = __fdividef(y, 1.0f + fabsf(y));
    }
    __syncthreads();
    for (int i = tid; i < NODES * NCLS; i += 256) {
        int nn = i / NCLS, cls = i - nn * NCLS;
        float s = linb[cls];
        #pragma unroll
        for (int o = 0; o < C2; o++) s = fmaf(Ysm[nn * C2 + o], linw[cls * C2 + o], s);
        out[i] = s;
    }
}

extern "C" void kernel_launch(void* const* d_in, const int* in_sizes, int n_in,
                              void* d_out, int out_size) {
    const float* x    = (const float*)d_in[0];
    const float* nb   = (const float*)d_in[1];
    const float* W1   = (const float*)d_in[2];
    const float* W2   = (const float*)d_in[3];
    const float* bn1w = (const float*)d_in[4];
    const float* bn1b = (const float*)d_in[5];
    const float* bn2w = (const float*)d_in[6];
    const float* bn2b = (const float*)d_in[7];
    const float* linw = (const float*)d_in[8];
    const float* linb = (const float*)d_in[9];
    float* out = (float*)d_out;

    k0_sum_nb<<<NODES, 256>>>(nb);
    k1_main<<<dim3(ATILES, NODES), 128>>>(x, nb, W1);
    k2_reduce<<<NODES, 256>>>();
    k3a_bn1x<<<1, 256>>>(bn1w, bn1b);
    k3b_layer2<<<NODES, 128>>>(W2, bn1w, bn1b);
    k3c_final<<<1, 256>>>(bn2w, bn2b, linw, linb, out);
}

// round 4
// speedup vs baseline: 1.1378x; 1.1378x over previous
#include <cuda_runtime.h>

#define NODES 64
#define KNB   32
#define FEAT  1024
#define C1    4
#define F1    16
#define O1    64        // C1*F1
#define C2    32
#define NCLS  10
#define JDIM  33        // self + 32 neighbors
#define ATILE 256       // a-rows per block (2 per thread)
#define ATILES 4        // FEAT / ATILE
#define PSLICES 8       // partial slices = ATILES * 2 halves
#define BTILE 256
#define BN_EPS 1e-5f

typedef unsigned long long ull;

// -------- scratch (no allocations allowed) --------
__device__ float g_S[NODES * FEAT];                       // 256 KB
__device__ float g_Pp[NODES * PSLICES * O1 * JDIM];       // 4.3 MB partial W1@R
__device__ float g_P[NODES * O1 * JDIM];                  // 540 KB
__device__ float g_bn1s[C1];
__device__ float g_bn1q[C1];
__device__ float g_x2p[NODES * C2];

// ---- packed f32x2 helpers (FFMA2 — ptxas won't emit it from C++) ----
__device__ __forceinline__ ull pk2(float lo, float hi) {
    ull r; asm("mov.b64 %0, {%1, %2};" : "=l"(r) : "f"(lo), "f"(hi)); return r;
}
__device__ __forceinline__ void fma2(ull& d, ull a, ull b) {
    asm("fma.rn.f32x2 %0, %1, %2, %0;" : "+l"(d) : "l"(a), "l"(b));
}
__device__ __forceinline__ float unpk_sum(ull v) {
    float lo, hi; asm("mov.b64 {%0, %1}, %2;" : "=f"(lo), "=f"(hi) : "l"(v));
    return lo + hi;
}

// adj = s/(|s|+1e-7), s = sign(t)*sqrt(max(|t|,1e-8))
// |adj| = 1/(1 + 1e-7*rsqrt(m)) ≈ 1 - 1e-7*rsqrt(m)   (err ≤ 1e-6 rel; saves a MUFU rcp)
__device__ __forceinline__ float adjf(float t) {
    float m = fmaxf(fabsf(t), 1e-8f);
    float v = fmaf(-1e-7f, rsqrtf(m), 1.0f);
    return (t > 0.0f) ? v : ((t < 0.0f) ? -v : 0.0f);
}

// K0: S[n,b] = sum_k nb[n,k,b]; block 0 also zeroes BN1 accumulators
__global__ void k0_sum_nb(const float* __restrict__ nb) {
    int n = blockIdx.x;
    if (n == 0 && threadIdx.x < C1) {
        g_bn1s[threadIdx.x] = 0.0f;
        g_bn1q[threadIdx.x] = 0.0f;
    }
    for (int b = threadIdx.x; b < FEAT; b += 256) {
        float s = 0.0f;
        #pragma unroll 8
        for (int k = 0; k < KNB; k++) s += nb[(n * KNB + k) * FEAT + b];
        g_S[n * FEAT + b] = s;
    }
}

// K1: per (node, 256-wide a-tile): each thread owns 2 adjacency rows.
//   R[a][j] = sum_b adj(a,b) * Y[j][b],  Y = [x ; nb_0..31]   (FFMA2 packed over b)
// epilogue per 128-row half: partial P[o][j] = sum_{a in half} W1[o][a] * R[a][j]
__global__ __launch_bounds__(128) void k1_main(
        const float* __restrict__ x,
        const float* __restrict__ nb,
        const float* __restrict__ W1) {
    __shared__ __align__(16) float smem[8704];   // 34.8 KB
    float* Ys = smem;                 // [33][256] phase A
    float* Ss = smem + JDIM * BTILE;  // [256]

    const int n   = blockIdx.y;
    const int at  = blockIdx.x;
    const int a0  = at * ATILE;
    const int tid = threadIdx.x;     // 128 threads, rows tid and tid+128

    const float xa0 = x[n * FEAT + a0 + tid];
    const float Sa0 = g_S[n * FEAT + a0 + tid];
    const float xa1 = x[n * FEAT + a0 + 128 + tid];
    const float Sa1 = g_S[n * FEAT + a0 + 128 + tid];

    ull acc0[JDIM], acc1[JDIM];
    #pragma unroll
    for (int j = 0; j < JDIM; j++) { acc0[j] = 0ull; acc1[j] = 0ull; }

    const float* xrow   = x + n * FEAT;
    const float* nbbase = nb + n * KNB * FEAT;

    for (int bt = 0; bt < FEAT; bt += BTILE) {
        __syncthreads();
        // stage Y tile: 33 rows x 64 float4
        for (int idx = tid; idx < JDIM * (BTILE / 4); idx += 128) {
            int j = idx >> 6, q = idx & 63;
            const float* src = (j == 0 ? xrow : nbbase + (j - 1) * FEAT) + bt + q * 4;
            ((float4*)Ys)[idx] = *(const float4*)src;
        }
        for (int idx = tid; idx < BTILE / 4; idx += 128)
            ((float4*)Ss)[idx] = *(const float4*)(g_S + n * FEAT + bt + idx * 4);
        __syncthreads();

        #pragma unroll 1
        for (int q = 0; q < BTILE / 4; q++) {
            float4 xb = ((float4*)Ys)[q];   // row j=0 is x
            float4 Sb = ((float4*)Ss)[q];
            // row 0 adjacency values (4 b-lanes)
            float a00 = adjf(fmaf(xa0, Sb.x, xb.x * Sa0));
            float a01 = adjf(fmaf(xa0, Sb.y, xb.y * Sa0));
            float a02 = adjf(fmaf(xa0, Sb.z, xb.z * Sa0));
            float a03 = adjf(fmaf(xa0, Sb.w, xb.w * Sa0));
            ull A0lo = pk2(a00, a01), A0hi = pk2(a02, a03);
            // row 1
            float a10 = adjf(fmaf(xa1, Sb.x, xb.x * Sa1));
            float a11 = adjf(fmaf(xa1, Sb.y, xb.y * Sa1));
            float a12 = adjf(fmaf(xa1, Sb.z, xb.z * Sa1));
            float a13 = adjf(fmaf(xa1, Sb.w, xb.w * Sa1));
            ull A1lo = pk2(a10, a11), A1hi = pk2(a12, a13);
            #pragma unroll
            for (int j = 0; j < JDIM; j++) {
                ulonglong2 y = ((const ulonglong2*)Ys)[j * 64 + q];  // broadcast
                fma2(acc0[j], A0lo, y.x);
                fma2(acc0[j], A0hi, y.y);
                fma2(acc1[j], A1lo, y.x);
                fma2(acc1[j], A1hi, y.y);
            }
        }
    }

    // ---- epilogue: fold W1 over each 128-row half of this a-tile ----
    float rr[JDIM];

#define EPI_HALF(H)                                                             \
    do {                                                                        \
        __syncthreads();                                                        \
        float* Rs = smem;               /* [128][34] */                         \
        float* Wt = smem + 128 * 34;    /* [32][129] */                         \
        _Pragma("unroll")                                                       \
        for (int j = 0; j < JDIM; j++) Rs[tid * 34 + j] = rr[j];                \
        __syncthreads();                                                        \
        for (int ot = 0; ot < O1; ot += 32) {                                   \
            for (int idx = tid; idx < 32 * 128; idx += 128) {                   \
                int oo = idx >> 7, i = idx & 127;                               \
                Wt[oo * 129 + i] = W1[(ot + oo) * FEAT + a0 + (H) * 128 + i];   \
            }                                                                   \
            __syncthreads();                                                    \
            for (int out = tid; out < 32 * JDIM; out += 128) {                  \
                int oo = out / JDIM, j = out - oo * JDIM;                       \
                float s0 = 0.0f, s1 = 0.0f;                                     \
                _Pragma("unroll 4")                                             \
                for (int i = 0; i < 128; i += 2) {                              \
                    s0 = fmaf(Wt[oo * 129 + i],     Rs[i * 34 + j],       s0);  \
                    s1 = fmaf(Wt[oo * 129 + i + 1], Rs[(i + 1) * 34 + j], s1);  \
                }                                                               \
                g_Pp[((n * PSLICES + at * 2 + (H)) * O1 + (ot + oo)) * JDIM + j] = s0 + s1; \
            }                                                                   \
            __syncthreads();                                                    \
        }                                                                       \
    } while (0)

    #pragma unroll
    for (int j = 0; j < JDIM; j++) rr[j] = unpk_sum(acc0[j]);
    EPI_HALF(0);
    #pragma unroll
    for (int j = 0; j < JDIM; j++) rr[j] = unpk_sum(acc1[j]);
    EPI_HALF(1);
#undef EPI_HALF
}

// K2: P[n] = sum over 8 partial slices; also accumulate BN1 x-path stats (j=0 elems)
__global__ void k2_reduce() {
    __shared__ float cs[C1], cq[C1];
    int n = blockIdx.x, tid = threadIdx.x;
    if (tid < C1) { cs[tid] = 0.0f; cq[tid] = 0.0f; }
    __syncthreads();
    for (int oj = tid; oj < O1 * JDIM; oj += 256) {
        float s = 0.0f;
        #pragma unroll
        for (int sl = 0; sl < PSLICES; sl++)
            s += g_Pp[(n * PSLICES + sl) * O1 * JDIM + oj];
        g_P[n * O1 * JDIM + oj] = s;
        int o = oj / JDIM;
        if (oj - o * JDIM == 0) {           // j == 0: x-path element
            atomicAdd(&cs[o >> 4], s);
            atomicAdd(&cq[o >> 4], s * s);
        }
    }
    __syncthreads();
    if (tid < C1) {
        atomicAdd(&g_bn1s[tid], cs[tid]);
        atomicAdd(&g_bn1q[tid], cq[tid]);
    }
}

// K3b: per node — BN1 (x: global stats from g_bn1s/q; nb: per-node) + full layer 2
__global__ __launch_bounds__(128) void k3b_layer2(
        const float* __restrict__ W2,
        const float* __restrict__ bn1w, const float* __restrict__ bn1b) {
    int n = blockIdx.x, tid = threadIdx.x;
    __shared__ float Ps[O1 * JDIM];
    __shared__ float x1s[O1];
    __shared__ float nb1s[KNB * O1];
    __shared__ float S2s[O1];
    __shared__ float xa2s[O1];
    __shared__ float als[C1], bes[C1];

    if (tid < C1) {
        float S = g_bn1s[tid], Q = g_bn1q[tid];
        float m = S * (1.0f / 1024.0f);
        float v = Q * (1.0f / 1024.0f) - m * m;
        float al = bn1w[tid] * rsqrtf(v + BN_EPS);
        als[tid] = al;
        bes[tid] = bn1b[tid] - m * al;
    }
    for (int i = tid; i < O1 * JDIM; i += 128) Ps[i] = g_P[n * O1 * JDIM + i];
    __syncthreads();

    if (tid < O1) {
        int c = tid >> 4;
        float y = fmaf(als[c], Ps[tid * JDIM], bes[c]);
        x1s[tid] = __fdividef(y, 1.0f + fabsf(y));
    }
    // neighbor BN: one warp per channel, lane = k
    {
        int c = tid >> 5, k = tid & 31;
        float s = 0.0f, q = 0.0f;
        #pragma unroll
        for (int f = 0; f < F1; f++) {
            float v = Ps[(c * F1 + f) * JDIM + 1 + k];
            s += v; q += v * v;
        }
        for (int off = 16; off; off >>= 1) {
            s += __shfl_down_sync(0xffffffffu, s, off);
            q += __shfl_down_sync(0xffffffffu, q, off);
        }
        float al = 0.0f, be = 0.0f;
        if (k == 0) {
            float m = s * (1.0f / 512.0f);
            float v = q * (1.0f / 512.0f) - m * m;
            al = bn1w[c] * rsqrtf(v + BN_EPS);
            be = bn1b[c] - m * al;
        }
        al = __shfl_sync(0xffffffffu, al, 0);
        be = __shfl_sync(0xffffffffu, be, 0);
        #pragma unroll
        for (int f = 0; f < F1; f++) {
            float y = fmaf(al, Ps[(c * F1 + f) * JDIM + 1 + k], be);
            nb1s[k * O1 + c * F1 + f] = __fdividef(y, 1.0f + fabsf(y));
        }
    }
    __syncthreads();
    if (tid < O1) {
        float s = 0.0f;
        #pragma unroll 8
        for (int k = 0; k < KNB; k++) s += nb1s[k * O1 + tid];
        S2s[tid] = s;
    }
    __syncthreads();
    // adj2 (denominator couples the 4 channels) fused into xa2
    if (tid < O1) {
        int c = tid >> 4, a = tid & 15;
        float acc = 0.0f;
        for (int b = 0; b < F1; b++) {
            float denom = 1e-7f, sc = 0.0f;
            #pragma unroll
            for (int c2 = 0; c2 < C1; c2++) {
                float t = x1s[c2 * F1 + a] * S2s[c2 * F1 + b]
                        + x1s[c2 * F1 + b] * S2s[c2 * F1 + a];
                float m = fmaxf(fabsf(t), 1e-8f);
                float r = m * rsqrtf(m);                 // sqrt(m)
                float sv = (t > 0.0f) ? r : ((t < 0.0f) ? -r : 0.0f);
                if (c2 == c) sc = sv;
                denom += fabsf(sv);
            }
            acc += __fdividef(sc, denom) * x1s[c * F1 + b];
        }
        xa2s[tid] = acc;
    }
    __syncthreads();
    if (tid < C2) {
        float s = 0.0f;
        #pragma unroll 8
        for (int i = 0; i < O1; i++) s = fmaf(W2[tid * O1 + i], xa2s[i], s);
        g_x2p[n * C2 + tid] = s;
    }
}

// K3c: BN2 (per channel over nodes) + softsign + final linear
__global__ void k3c_final(const float* __restrict__ bn2w, const float* __restrict__ bn2b,
                          const float* __restrict__ linw, const float* __restrict__ linb,
                          float* __restrict__ out) {
    __shared__ float Ysm[NODES * C2];
    __shared__ float als[C2], bes[C2];
    int tid = threadIdx.x;  // 256
    if (tid < C2) {
        float s = 0.0f, q = 0.0f;
        for (int nn = 0; nn < NODES; nn++) {
            float v = g_x2p[nn * C2 + tid];
            s += v; q += v * v;
        }
        float m = s * (1.0f / 64.0f);
        float v = q * (1.0f / 64.0f) - m * m;
        float al = bn2w[tid] * rsqrtf(v + BN_EPS);
        als[tid] = al;
        bes[tid] = bn2b[tid] - m * al;
    }
    __syncthreads();
    for (int i = tid; i < NODES * C2; i += 256) {
        int o = i & (C2 - 1);
        float y = fmaf(als[o], g_x2p[i], bes[o]);
        Ysm[i] = __fdividef(y, 1.0f + fabsf(y));
    }
    __syncthreads();
    for (int i = tid; i < NODES * NCLS; i += 256) {
        int nn = i / NCLS, cls = i - nn * NCLS;
        float s = linb[cls];
        #pragma unroll
        for (int o = 0; o < C2; o++) s = fmaf(Ysm[nn * C2 + o], linw[cls * C2 + o], s);
        out[i] = s;
    }
}

extern "C" void kernel_launch(void* const* d_in, const int* in_sizes, int n_in,
                              void* d_out, int out_size) {
    const float* x    = (const float*)d_in[0];
    const float* nb   = (const float*)d_in[1];
    const float* W1   = (const float*)d_in[2];
    const float* W2   = (const float*)d_in[3];
    const float* bn1w = (const float*)d_in[4];
    const float* bn1b = (const float*)d_in[5];
    const float* bn2w = (const float*)d_in[6];
    const float* bn2b = (const float*)d_in[7];
    const float* linw = (const float*)d_in[8];
    const float* linb = (const float*)d_in[9];
    float* out = (float*)d_out;

    k0_sum_nb<<<NODES, 256>>>(nb);
    k1_main<<<dim3(ATILES, NODES), 128>>>(x, nb, W1);
    k2_reduce<<<NODES, 256>>>();
    k3b_layer2<<<NODES, 128>>>(W2, bn1w, bn1b);
    k3c_final<<<1, 256>>>(bn2w, bn2b, linw, linb, out);
}

// round 6
// speedup vs baseline: 1.2443x; 1.0935x over previous
#include <cuda_runtime.h>

#define NODES 64
#define KNB   32
#define FEAT  1024
#define C1    4
#define F1    16
#define O1    64        // C1*F1
#define C2    32
#define NCLS  10
#define JDIM  33        // self + 32 neighbors
#define ATILE 256       // a-rows per block (2 per thread)
#define ATILES 4        // FEAT / ATILE
#define PSLICES 8       // partial slices = ATILES * 2 halves
#define BTILE 256
#define BN_EPS 1e-5f

typedef unsigned long long ull;

// -------- scratch (no allocations allowed) --------
__device__ float g_S[NODES * FEAT];                       // 256 KB
__device__ float g_Pp[NODES * PSLICES * O1 * JDIM];       // 4.3 MB partial W1@R
__device__ float g_P[NODES * O1 * JDIM];                  // 540 KB
__device__ float g_bn1s[C1];
__device__ float g_bn1q[C1];
__device__ float g_x2p[NODES * C2];

// ---- packed f32x2 helpers ----
__device__ __forceinline__ ull pk2(float lo, float hi) {
    ull r; asm("mov.b64 %0, {%1, %2};" : "=l"(r) : "f"(lo), "f"(hi)); return r;
}
__device__ __forceinline__ void fma2(ull& d, ull a, ull b) {
    asm("fma.rn.f32x2 %0, %1, %2, %0;" : "+l"(d) : "l"(a), "l"(b));
}
__device__ __forceinline__ ull fma2d(ull a, ull b, ull c) {
    ull d; asm("fma.rn.f32x2 %0, %1, %2, %3;" : "=l"(d) : "l"(a), "l"(b), "l"(c)); return d;
}
__device__ __forceinline__ ull mul2(ull a, ull b) {
    ull d; asm("mul.rn.f32x2 %0, %1, %2;" : "=l"(d) : "l"(a), "l"(b)); return d;
}
__device__ __forceinline__ float unpk_sum(ull v) {
    float lo, hi; asm("mov.b64 {%0, %1}, %2;" : "=f"(lo), "=f"(hi) : "l"(v));
    return lo + hi;
}
// packed sign: each 32-bit half -> +/-1.0f carrying t's sign (adj ~= sign(t); C=1
// makes sqrt/normalization cancel to within <=1e-3 only at |t|<=1e-8 — negligible)
__device__ __forceinline__ ull sgn2(ull t) {
    unsigned lo = (unsigned)t, hi = (unsigned)(t >> 32);
    lo = (lo & 0x80000000u) | 0x3f800000u;
    hi = (hi & 0x80000000u) | 0x3f800000u;
    return (ull)lo | ((ull)hi << 32);
}

// K0: S[n,b] = sum_k nb[n,k,b] (vectorized)
__global__ void k0_sum_nb(const float* __restrict__ nb) {
    int n = blockIdx.x;
    int q = threadIdx.x;                       // 256 threads = 256 float4 columns
    float4 s = make_float4(0.f, 0.f, 0.f, 0.f);
    const float4* base = (const float4*)(nb + n * KNB * FEAT);
    #pragma unroll 8
    for (int k = 0; k < KNB; k++) {
        float4 v = base[k * (FEAT / 4) + q];
        s.x += v.x; s.y += v.y; s.z += v.z; s.w += v.w;
    }
    ((float4*)(g_S + n * FEAT))[q] = s;
}

// launch-order fillers (ncu captures launch #4 -> make it k1)
__global__ void kinit_stats() {
    if (threadIdx.x < C1) { g_bn1s[threadIdx.x] = 0.0f; g_bn1q[threadIdx.x] = 0.0f; }
}
__global__ void kpre() {}

// K1: per (node, 256-wide a-tile): each thread owns 2 adjacency rows.
//   R[a][j] = sum_b sign(x_a S_b + x_b S_a) * Y[j][b],  Y = [x ; nb_0..31]
// epilogue per 128-row half: partial P[o][j] = sum_{a in half} W1[o][a] * R[a][j]
__global__ __launch_bounds__(128, 2) void k1_main(
        const float* __restrict__ x,
        const float* __restrict__ nb,
        const float* __restrict__ W1) {
    __shared__ __align__(16) float smem[8704];   // 34.8 KB
    float* Ys = smem;                 // [33][256] phase A
    float* Ss = smem + JDIM * BTILE;  // [256]

    const int n   = blockIdx.y;
    const int at  = blockIdx.x;
    const int a0  = at * ATILE;
    const int tid = threadIdx.x;     // 128 threads, rows tid and tid+128

    const float xa0 = x[n * FEAT + a0 + tid];
    const float Sa0 = g_S[n * FEAT + a0 + tid];
    const float xa1 = x[n * FEAT + a0 + 128 + tid];
    const float Sa1 = g_S[n * FEAT + a0 + 128 + tid];
    const ull xa0p = pk2(xa0, xa0), Sa0p = pk2(Sa0, Sa0);
    const ull xa1p = pk2(xa1, xa1), Sa1p = pk2(Sa1, Sa1);

    ull acc0[JDIM], acc1[JDIM];
    #pragma unroll
    for (int j = 0; j < JDIM; j++) { acc0[j] = 0ull; acc1[j] = 0ull; }

    const float* xrow   = x + n * FEAT;
    const float* nbbase = nb + n * KNB * FEAT;

    for (int bt = 0; bt < FEAT; bt += BTILE) {
        __syncthreads();
        // stage Y tile: 33 rows x 64 float4
        for (int idx = tid; idx < JDIM * (BTILE / 4); idx += 128) {
            int j = idx >> 6, q = idx & 63;
            const float* src = (j == 0 ? xrow : nbbase + (j - 1) * FEAT) + bt + q * 4;
            ((float4*)Ys)[idx] = *(const float4*)src;
        }
        for (int idx = tid; idx < BTILE / 4; idx += 128)
            ((float4*)Ss)[idx] = *(const float4*)(g_S + n * FEAT + bt + idx * 4);
        __syncthreads();

        #pragma unroll 1
        for (int q = 0; q < BTILE / 4; q++) {
            ulonglong2 xb2 = ((const ulonglong2*)Ys)[q];   // row j=0 is x
            ulonglong2 Sb2 = ((const ulonglong2*)Ss)[q];
            // packed adjacency signs, 2 rows x 4 b-lanes
            ull A0lo = sgn2(fma2d(xa0p, Sb2.x, mul2(Sa0p, xb2.x)));
            ull A0hi = sgn2(fma2d(xa0p, Sb2.y, mul2(Sa0p, xb2.y)));
            ull A1lo = sgn2(fma2d(xa1p, Sb2.x, mul2(Sa1p, xb2.x)));
            ull A1hi = sgn2(fma2d(xa1p, Sb2.y, mul2(Sa1p, xb2.y)));
            #pragma unroll
            for (int j = 0; j < JDIM; j++) {
                ulonglong2 y = ((const ulonglong2*)Ys)[j * 64 + q];  // broadcast
                fma2(acc0[j], A0lo, y.x);
                fma2(acc1[j], A1lo, y.x);
                fma2(acc0[j], A0hi, y.y);
                fma2(acc1[j], A1hi, y.y);
            }
        }
    }

    // ---- epilogue: fold W1 over each 128-row half of this a-tile ----
    float rr[JDIM];

#define EPI_HALF(H)                                                             \
    do {                                                                        \
        __syncthreads();                                                        \
        float* Rs = smem;               /* [128][34] */                         \
        float* Wt = smem + 128 * 34;    /* [32][129] */                         \
        _Pragma("unroll")                                                       \
        for (int j = 0; j < JDIM; j++) Rs[tid * 34 + j] = rr[j];                \
        __syncthreads();                                                        \
        for (int ot = 0; ot < O1; ot += 32) {                                   \
            for (int idx = tid; idx < 32 * 128; idx += 128) {                   \
                int oo = idx >> 7, i = idx & 127;                               \
                Wt[oo * 129 + i] = W1[(ot + oo) * FEAT + a0 + (H) * 128 + i];   \
            }                                                                   \
            __syncthreads();                                                    \
            for (int out = tid; out < 32 * JDIM; out += 128) {                  \
                int oo = out / JDIM, j = out - oo * JDIM;                       \
                float s0 = 0.0f, s1 = 0.0f;                                     \
                _Pragma("unroll 4")                                             \
                for (int i = 0; i < 128; i += 2) {                              \
                    s0 = fmaf(Wt[oo * 129 + i],     Rs[i * 34 + j],       s0);  \
                    s1 = fmaf(Wt[oo * 129 + i + 1], Rs[(i + 1) * 34 + j], s1);  \
                }                                                               \
                g_Pp[((n * PSLICES + at * 2 + (H)) * O1 + (ot + oo)) * JDIM + j] = s0 + s1; \
            }                                                                   \
            __syncthreads();                                                    \
        }                                                                       \
    } while (0)

    #pragma unroll
    for (int j = 0; j < JDIM; j++) rr[j] = unpk_sum(acc0[j]);
    EPI_HALF(0);
    #pragma unroll
    for (int j = 0; j < JDIM; j++) rr[j] = unpk_sum(acc1[j]);
    EPI_HALF(1);
#undef EPI_HALF
}

// K2: P[n] = sum over 8 partial slices; also accumulate BN1 x-path stats (j=0 elems)
__global__ void k2_reduce() {
    __shared__ float cs[C1], cq[C1];
    int n = blockIdx.x, tid = threadIdx.x;
    if (tid < C1) { cs[tid] = 0.0f; cq[tid] = 0.0f; }
    __syncthreads();
    for (int oj = tid; oj < O1 * JDIM; oj += 256) {
        float s = 0.0f;
        #pragma unroll
        for (int sl = 0; sl < PSLICES; sl++)
            s += g_Pp[(n * PSLICES + sl) * O1 * JDIM + oj];
        g_P[n * O1 * JDIM + oj] = s;
        int o = oj / JDIM;
        if (oj - o * JDIM == 0) {           // j == 0: x-path element
            atomicAdd(&cs[o >> 4], s);
            atomicAdd(&cq[o >> 4], s * s);
        }
    }
    __syncthreads();
    if (tid < C1) {
        atomicAdd(&g_bn1s[tid], cs[tid]);
        atomicAdd(&g_bn1q[tid], cq[tid]);
    }
}

// K3b: per node — BN1 (x: global stats; nb: per-node) + full layer 2
__global__ __launch_bounds__(128) void k3b_layer2(
        const float* __restrict__ W2,
        const float* __restrict__ bn1w, const float* __restrict__ bn1b) {
    int n = blockIdx.x, tid = threadIdx.x;
    __shared__ __align__(16) float Ps[O1 * JDIM];
    __shared__ float x1s[O1];
    __shared__ float nb1s[KNB * O1];
    __shared__ float S2s[O1];
    __shared__ float xa2a[O1], xa2b[O1];
    __shared__ float als[C1], bes[C1];

    if (tid < C1) {
        float S = g_bn1s[tid], Q = g_bn1q[tid];
        float m = S * (1.0f / 1024.0f);
        float v = Q * (1.0f / 1024.0f) - m * m;
        float al = bn1w[tid] * rsqrtf(v + BN_EPS);
        als[tid] = al;
        bes[tid] = bn1b[tid] - m * al;
    }
    // vectorized load of P[n]: 2112 floats = 528 float4
    {
        const float4* src = (const float4*)(g_P + n * O1 * JDIM);
        #pragma unroll
        for (int i = 0; i < 4; i++)
            ((float4*)Ps)[tid + i * 128] = src[tid + i * 128];
        if (tid < 16) ((float4*)Ps)[512 + tid] = src[512 + tid];
    }
    __syncthreads();

    if (tid < O1) {
        int c = tid >> 4;
        float y = fmaf(als[c], Ps[tid * JDIM], bes[c]);
        x1s[tid] = __fdividef(y, 1.0f + fabsf(y));
    }
    // neighbor BN: one warp per channel, lane = k
    {
        int c = tid >> 5, k = tid & 31;
        float s = 0.0f, q = 0.0f;
        #pragma unroll
        for (int f = 0; f < F1; f++) {
            float v = Ps[(c * F1 + f) * JDIM + 1 + k];
            s += v; q += v * v;
        }
        for (int off = 16; off; off >>= 1) {
            s += __shfl_down_sync(0xffffffffu, s, off);
            q += __shfl_down_sync(0xffffffffu, q, off);
        }
        float al = 0.0f, be = 0.0f;
        if (k == 0) {
            float m = s * (1.0f / 512.0f);
            float v = q * (1.0f / 512.0f) - m * m;
            al = bn1w[c] * rsqrtf(v + BN_EPS);
            be = bn1b[c] - m * al;
        }
        al = __shfl_sync(0xffffffffu, al, 0);
        be = __shfl_sync(0xffffffffu, be, 0);
        #pragma unroll
        for (int f = 0; f < F1; f++) {
            float y = fmaf(al, Ps[(c * F1 + f) * JDIM + 1 + k], be);
            nb1s[k * O1 + c * F1 + f] = __fdividef(y, 1.0f + fabsf(y));
        }
    }
    __syncthreads();
    if (tid < O1) {
        float s = 0.0f;
        #pragma unroll 8
        for (int k = 0; k < KNB; k++) s += nb1s[k * O1 + tid];
        S2s[tid] = s;
    }
    __syncthreads();
    // adj2 fused into xa2; each (c,a) item split over 2 threads (b halves)
    {
        int item = tid & 63, half = tid >> 6;
        int c = item >> 4, a = item & 15;
        float acc = 0.0f;
        #pragma unroll
        for (int bb = 0; bb < 8; bb++) {
            int b = half * 8 + bb;
            float denom = 1e-7f, sc = 0.0f;
            #pragma unroll
            for (int c2 = 0; c2 < C1; c2++) {
                float t = x1s[c2 * F1 + a] * S2s[c2 * F1 + b]
                        + x1s[c2 * F1 + b] * S2s[c2 * F1 + a];
                float m = fmaxf(fabsf(t), 1e-8f);
                float r = m * rsqrtf(m);                 // sqrt(m)
                float sv = (t > 0.0f) ? r : ((t < 0.0f) ? -r : 0.0f);
                if (c2 == c) sc = sv;
                denom += fabsf(sv);
            }
            acc += __fdividef(sc, denom) * x1s[c * F1 + b];
        }
        (half ? xa2b : xa2a)[item] = acc;
    }
    __syncthreads();
    if (tid < C2) {
        float s = 0.0f;
        #pragma unroll 8
        for (int i = 0; i < O1; i++)
            s = fmaf(W2[tid * O1 + i], xa2a[i] + xa2b[i], s);
        g_x2p[n * C2 + tid] = s;
    }
}

// K3c: BN2 (per channel over nodes) + softsign + final linear
__global__ void k3c_final(const float* __restrict__ bn2w, const float* __restrict__ bn2b,
                          const float* __restrict__ linw, const float* __restrict__ linb,
                          float* __restrict__ out) {
    __shared__ float Ysm[NODES * C2];
    __shared__ float als[C2], bes[C2];
    int tid = threadIdx.x;  // 256
    if (tid < C2) {
        float s = 0.0f, q = 0.0f;
        for (int nn = 0; nn < NODES; nn++) {
            float v = g_x2p[nn * C2 + tid];
            s += v; q += v * v;
        }
        float m = s * (1.0f / 64.0f);
        float v = q * (1.0f / 64.0f) - m * m;
        float al = bn2w[tid] * rsqrtf(v + BN_EPS);
        als[tid] = al;
        bes[tid] = bn2b[tid] - m * al;
    }
    __syncthreads();
    for (int i = tid; i < NODES * C2; i += 256) {
        int o = i & (C2 - 1);
        float y = fmaf(als[o], g_x2p[i], bes[o]);
        Ysm[i] = __fdividef(y, 1.0f + fabsf(y));
    }
    __syncthreads();
    for (int i = tid; i < NODES * NCLS; i += 256) {
        int nn = i / NCLS, cls = i - nn * NCLS;
        float s = linb[cls];
        #pragma unroll
        for (int o = 0; o < C2; o++) s = fmaf(Ysm[nn * C2 + o], linw[cls * C2 + o], s);
        out[i] = s;
    }
}

extern "C" void kernel_launch(void* const* d_in, const int* in_sizes, int n_in,
                              void* d_out, int out_size) {
    const float* x    = (const float*)d_in[0];
    const float* nb   = (const float*)d_in[1];
    const float* W1   = (const float*)d_in[2];
    const float* W2   = (const float*)d_in[3];
    const float* bn1w = (const float*)d_in[4];
    const float* bn1b = (const float*)d_in[5];
    const float* bn2w = (const float*)d_in[6];
    const float* bn2b = (const float*)d_in[7];
    const float* linw = (const float*)d_in[8];
    const float* linb = (const float*)d_in[9];
    float* out = (float*)d_out;

    k0_sum_nb<<<NODES, 256>>>(nb);          // launch 1
    kinit_stats<<<1, 32>>>();               // launch 2
    kpre<<<1, 32>>>();                      // launch 3 (filler so k1 is #4 for ncu)
    k1_main<<<dim3(ATILES, NODES), 128>>>(x, nb, W1);   // launch 4 <- profiled
    k2_reduce<<<NODES, 256>>>();
    k3b_layer2<<<NODES, 128>>>(W2, bn1w, bn1b);
    k3c_final<<<1, 256>>>(bn2w, bn2b, linw, linb, out);
}